// round 3
// baseline (speedup 1.0000x reference)
#include <cuda_runtime.h>
#include <cuda_bf16.h>
#include <cstdint>

// ---------------------------------------------------------------------------
// LastAggregator: out[n, :] = msg[argmax_{i : index[i]==n} t[i], :]
// (ties -> smallest i; empty segments -> zeros)
//
// Strategy:
//   key(i) = (total_order(t[i]) << 32) | ~i    packed into u64
//   atomicMax over keys per segment  ->  winner = ~(low 32 bits)
//   key == 0  <=>  empty segment (valid keys have nonzero low word).
//
// NOTE: index arrives as int32 (JAX default config downcasts the declared
// int64 — x64 disabled), so it is read as const int*.
// ---------------------------------------------------------------------------

#define MAX_SEGMENTS (1 << 17)  // 131072 >= N = 65536
__device__ unsigned long long g_key[MAX_SEGMENTS];

__global__ void la_init_kernel(int N) {
    int i = blockIdx.x * blockDim.x + threadIdx.x;
    if (i < N) g_key[i] = 0ull;
}

// 2 events per thread.
__global__ void la_argmax_kernel(const int* __restrict__ index,
                                 const float* __restrict__ t,
                                 int M, int N) {
    int base = (blockIdx.x * blockDim.x + threadIdx.x) * 2;
#pragma unroll
    for (int k = 0; k < 2; ++k) {
        int i = base + k;
        if (i >= M) return;
        int seg = index[i];
        unsigned int fb  = __float_as_uint(t[i]);
        // Total order on float bits: monotone in value for +/- floats.
        unsigned int ord = (fb & 0x80000000u) ? ~fb : (fb | 0x80000000u);
        unsigned long long key =
            ((unsigned long long)ord << 32) | (unsigned long long)(~(unsigned int)i);
        if (seg >= 0 && seg < N)              // defensive bound (1 ISETP)
            atomicMax(&g_key[seg], key);
    }
}

// D=256 specialized gather: 32 threads per output row; each thread writes
// 2 float4s (lanes l and l+32) of its row.
__global__ void la_gather_d256_kernel(const float4* __restrict__ msg,
                                      float4* __restrict__ out,
                                      int N) {
    int tid  = blockIdx.x * blockDim.x + threadIdx.x;
    int row  = tid >> 5;          // 32 threads per row
    int lane = tid & 31;          // lanes lane and lane+32
    if (row >= N) return;

    unsigned long long key = g_key[row];
    size_t obase = (size_t)row * 64;
    if (key != 0ull) {
        unsigned int win = ~(unsigned int)(key & 0xFFFFFFFFull);
        size_t ibase = (size_t)win * 64;
        float4 v0 = __ldg(&msg[ibase + lane]);
        float4 v1 = __ldg(&msg[ibase + lane + 32]);
        out[obase + lane]      = v0;
        out[obase + lane + 32] = v1;
    } else {
        float4 z = make_float4(0.f, 0.f, 0.f, 0.f);
        out[obase + lane]      = z;
        out[obase + lane + 32] = z;
    }
}

// Generic fallback (one float4 per thread) for unexpected D.
__global__ void la_gather_generic_kernel(const float4* __restrict__ msg,
                                         float4* __restrict__ out,
                                         int N, int D4) {
    long long e = (long long)blockIdx.x * blockDim.x + threadIdx.x;
    long long total = (long long)N * D4;
    if (e >= total) return;
    int row  = (int)(e / D4);
    int lane = (int)(e % D4);
    unsigned long long key = g_key[row];
    float4 v = make_float4(0.f, 0.f, 0.f, 0.f);
    if (key != 0ull) {
        unsigned int win = ~(unsigned int)(key & 0xFFFFFFFFull);
        v = __ldg(&msg[(size_t)win * D4 + lane]);
    }
    out[(size_t)row * D4 + lane] = v;
}

extern "C" void kernel_launch(void* const* d_in, const int* in_sizes, int n_in,
                              void* d_out, int out_size) {
    // metadata order: msg [M*D f32], index [M i32], t [M f32], (dim_size)
    const float* msg   = (const float*)d_in[0];
    const int*   index = (const int*)d_in[1];
    const float* t     = (const float*)d_in[2];
    float*       out   = (float*)d_out;

    int M = in_sizes[1];              // 262144
    int D = in_sizes[0] / M;          // 256
    int N = out_size / D;             // 65536
    if (N > MAX_SEGMENTS) N = MAX_SEGMENTS;  // never exceed scratch

    // 1) clear keys
    {
        int threads = 256;
        int blocks  = (N + threads - 1) / threads;
        la_init_kernel<<<blocks, threads>>>(N);
    }
    // 2) segment argmax via packed atomicMax (2 events/thread)
    {
        int threads = 256;
        int per_blk = threads * 2;
        int blocks  = (M + per_blk - 1) / per_blk;
        la_argmax_kernel<<<blocks, threads>>>(index, t, M, N);
    }
    // 3) gather winner rows (or zeros) into output
    if (D == 256) {
        int threads = 128;
        long long total_threads = (long long)N * 32;
        int blocks = (int)((total_threads + threads - 1) / threads);
        la_gather_d256_kernel<<<blocks, threads>>>((const float4*)msg,
                                                   (float4*)out, N);
    } else {
        int D4 = D / 4;
        long long total = (long long)N * D4;
        int threads = 256;
        int blocks  = (int)((total + threads - 1) / threads);
        la_gather_generic_kernel<<<blocks, threads>>>((const float4*)msg,
                                                      (float4*)out, N, D4);
    }
}

// round 4
// speedup vs baseline: 1.0503x; 1.0503x over previous
#include <cuda_runtime.h>
#include <cuda_bf16.h>
#include <cstdint>

// ---------------------------------------------------------------------------
// LastAggregator: out[n, :] = msg[argmax_{i : index[i]==n} t[i], :]
// (ties -> smallest i; empty segments -> zeros)
//
//   key(i) = (total_order(t[i]) << 32) | ~i    packed into u64
//   atomicMax over keys per segment  ->  winner = ~(low 32 bits)
//   key == 0  <=>  empty segment (valid keys have nonzero low word).
//
// Self-cleaning: the gather kernel resets each consumed key to 0, so no
// separate init pass is needed (device globals start zero-initialized,
// and every call leaves the array cleared -> identical work per call).
//
// index arrives as int32 (JAX x64 disabled downcasts the declared int64).
// ---------------------------------------------------------------------------

#define MAX_SEGMENTS (1 << 17)  // 131072 >= N = 65536
__device__ unsigned long long g_key[MAX_SEGMENTS];

// --- argmax: 4 events per thread, vectorized loads --------------------------
__global__ void la_argmax_kernel(const int* __restrict__ index,
                                 const float* __restrict__ t,
                                 int M, int N) {
    int base = (blockIdx.x * blockDim.x + threadIdx.x) * 4;
    if (base + 3 < M) {
        int4   s  = *reinterpret_cast<const int4*>(index + base);
        float4 tv = *reinterpret_cast<const float4*>(t + base);
        int   segs[4] = {s.x, s.y, s.z, s.w};
        float ts[4]   = {tv.x, tv.y, tv.z, tv.w};
#pragma unroll
        for (int k = 0; k < 4; ++k) {
            unsigned int fb  = __float_as_uint(ts[k]);
            unsigned int ord = (fb & 0x80000000u) ? ~fb : (fb | 0x80000000u);
            unsigned int i   = (unsigned int)(base + k);
            unsigned long long key =
                ((unsigned long long)ord << 32) | (unsigned long long)(~i);
            int seg = segs[k];
            if (seg >= 0 && seg < N) atomicMax(&g_key[seg], key);
        }
    } else {
        for (int i = base; i < M; ++i) {
            int seg = index[i];
            unsigned int fb  = __float_as_uint(t[i]);
            unsigned int ord = (fb & 0x80000000u) ? ~fb : (fb | 0x80000000u);
            unsigned long long key =
                ((unsigned long long)ord << 32) |
                (unsigned long long)(~(unsigned int)i);
            if (seg >= 0 && seg < N) atomicMax(&g_key[seg], key);
        }
    }
}

// --- D=256 gather: one warp per row; self-cleans the key --------------------
__global__ void la_gather_d256_kernel(const float4* __restrict__ msg,
                                      float4* __restrict__ out,
                                      int N) {
    int tid  = blockIdx.x * blockDim.x + threadIdx.x;
    int row  = tid >> 5;          // one full warp per row
    int lane = tid & 31;
    if (row >= N) return;

    unsigned long long key = 0ull;
    if (lane == 0) key = g_key[row];
    key = __shfl_sync(0xffffffffu, key, 0);     // broadcast + warp sync
    if (lane == 0) g_key[row] = 0ull;           // self-clean for next call

    size_t obase = (size_t)row * 64;
    if (key != 0ull) {
        unsigned int win = ~(unsigned int)(key & 0xFFFFFFFFull);
        size_t ibase = (size_t)win * 64;
        float4 v0 = __ldg(&msg[ibase + lane]);
        float4 v1 = __ldg(&msg[ibase + lane + 32]);
        out[obase + lane]      = v0;
        out[obase + lane + 32] = v1;
    } else {
        float4 z = make_float4(0.f, 0.f, 0.f, 0.f);
        out[obase + lane]      = z;
        out[obase + lane + 32] = z;
    }
}

// --- generic fallback (unexpected D): init + gather -------------------------
__global__ void la_init_kernel(int N) {
    int i = blockIdx.x * blockDim.x + threadIdx.x;
    if (i < N) g_key[i] = 0ull;
}

__global__ void la_gather_generic_kernel(const float4* __restrict__ msg,
                                         float4* __restrict__ out,
                                         int N, int D4) {
    long long e = (long long)blockIdx.x * blockDim.x + threadIdx.x;
    long long total = (long long)N * D4;
    if (e >= total) return;
    int row  = (int)(e / D4);
    int lane = (int)(e % D4);
    unsigned long long key = g_key[row];
    float4 v = make_float4(0.f, 0.f, 0.f, 0.f);
    if (key != 0ull) {
        unsigned int win = ~(unsigned int)(key & 0xFFFFFFFFull);
        v = __ldg(&msg[(size_t)win * D4 + lane]);
    }
    out[(size_t)row * D4 + lane] = v;
    if (lane == 0) g_key[row] = 0ull;  // note: generic path still re-inits below
}

extern "C" void kernel_launch(void* const* d_in, const int* in_sizes, int n_in,
                              void* d_out, int out_size) {
    // metadata order: msg [M*D f32], index [M i32], t [M f32], (dim_size)
    const float* msg   = (const float*)d_in[0];
    const int*   index = (const int*)d_in[1];
    const float* t     = (const float*)d_in[2];
    float*       out   = (float*)d_out;

    int M = in_sizes[1];              // 262144
    int D = in_sizes[0] / M;          // 256
    int N = out_size / D;             // 65536
    if (N > MAX_SEGMENTS) N = MAX_SEGMENTS;

    if (D == 256) {
        // argmax: 4 events/thread
        {
            int threads = 256;
            int per_blk = threads * 4;
            int blocks  = (M + per_blk - 1) / per_blk;
            la_argmax_kernel<<<blocks, threads>>>(index, t, M, N);
        }
        // gather (self-cleaning)
        {
            int threads = 256;
            long long total_threads = (long long)N * 32;
            int blocks = (int)((total_threads + threads - 1) / threads);
            la_gather_d256_kernel<<<blocks, threads>>>((const float4*)msg,
                                                       (float4*)out, N);
        }
    } else {
        // generic safe path: explicit init + argmax + gather
        {
            int threads = 256;
            int blocks  = (N + threads - 1) / threads;
            la_init_kernel<<<blocks, threads>>>(N);
        }
        {
            int threads = 256;
            int per_blk = threads * 4;
            int blocks  = (M + per_blk - 1) / per_blk;
            la_argmax_kernel<<<blocks, threads>>>(index, t, M, N);
        }
        {
            int D4 = D / 4;
            long long total = (long long)N * D4;
            int threads = 256;
            int blocks  = (int)((total + threads - 1) / threads);
            la_gather_generic_kernel<<<blocks, threads>>>((const float4*)msg,
                                                          (float4*)out, N, D4);
        }
    }
}

// round 5
// speedup vs baseline: 1.2490x; 1.1892x over previous
#include <cuda_runtime.h>
#include <cuda_bf16.h>
#include <cstdint>

// ---------------------------------------------------------------------------
// LastAggregator: out[n, :] = msg[argmax_{i : index[i]==n} t[i], :]
// (ties -> smallest i; empty segments -> zeros)
//
//   key(i) = (total_order(t[i]) << 32) | ~i    packed into u64
//   atomicMax over keys per segment  ->  winner = ~(low 32 bits)
//   key == 0  <=>  empty segment (valid keys have nonzero low word).
//
// Self-cleaning: the gather kernel resets each consumed key to 0, so no
// separate init pass is needed (device globals start zero-initialized,
// and every call leaves the array cleared -> identical work per call).
//
// index arrives as int32 (JAX x64 disabled downcasts the declared int64).
// ---------------------------------------------------------------------------

#define MAX_SEGMENTS (1 << 17)  // 131072 >= N = 65536
__device__ unsigned long long g_key[MAX_SEGMENTS];

__device__ __forceinline__ void stcs_f4(float4* p, float4 v) {
    // streaming store: don't pollute L2 with write-once output
    asm volatile("st.global.cs.v4.f32 [%0], {%1,%2,%3,%4};"
                 :: "l"(p), "f"(v.x), "f"(v.y), "f"(v.z), "f"(v.w) : "memory");
}

__device__ __forceinline__ unsigned long long
make_key(float tv, unsigned int i) {
    unsigned int fb  = __float_as_uint(tv);
    unsigned int ord = (fb & 0x80000000u) ? ~fb : (fb | 0x80000000u);
    return ((unsigned long long)ord << 32) | (unsigned long long)(~i);
}

// --- argmax: 8 events per thread, vectorized loads --------------------------
__global__ void la_argmax_kernel(const int* __restrict__ index,
                                 const float* __restrict__ t,
                                 int M, int N) {
    int base = (blockIdx.x * blockDim.x + threadIdx.x) * 8;
    if (base + 7 < M) {
        int4   s0 = *reinterpret_cast<const int4*>(index + base);
        int4   s1 = *reinterpret_cast<const int4*>(index + base + 4);
        float4 t0 = *reinterpret_cast<const float4*>(t + base);
        float4 t1 = *reinterpret_cast<const float4*>(t + base + 4);
        int   segs[8] = {s0.x, s0.y, s0.z, s0.w, s1.x, s1.y, s1.z, s1.w};
        float ts[8]   = {t0.x, t0.y, t0.z, t0.w, t1.x, t1.y, t1.z, t1.w};
#pragma unroll
        for (int k = 0; k < 8; ++k) {
            unsigned long long key = make_key(ts[k], (unsigned int)(base + k));
            int seg = segs[k];
            if (seg >= 0 && seg < N) atomicMax(&g_key[seg], key);
        }
    } else {
        for (int i = base; i < M; ++i) {
            unsigned long long key = make_key(t[i], (unsigned int)i);
            int seg = index[i];
            if (seg >= 0 && seg < N) atomicMax(&g_key[seg], key);
        }
    }
}

// --- D=256 gather: one warp per 2 rows; self-cleans keys --------------------
// Each thread carries 2 independent key->data chains (4 LDG.128 + 4 STG.128).
__global__ void la_gather_d256_kernel(const float4* __restrict__ msg,
                                      float4* __restrict__ out,
                                      int N) {
    int gwarp = (blockIdx.x * blockDim.x + threadIdx.x) >> 5;
    int lane  = threadIdx.x & 31;
    int r0 = gwarp * 2;
    int r1 = r0 + 1;
    if (r0 >= N) return;
    bool has1 = (r1 < N);

    // lanes 0/1 fetch the two keys in parallel, broadcast to all lanes
    unsigned long long kk = 0ull;
    if (lane == 0)            kk = g_key[r0];
    else if (lane == 1 && has1) kk = g_key[r1];
    unsigned long long key0 = __shfl_sync(0xffffffffu, kk, 0);
    unsigned long long key1 = __shfl_sync(0xffffffffu, kk, 1);
    // self-clean for next call (after all lanes hold the values)
    if (lane == 0)            g_key[r0] = 0ull;
    else if (lane == 1 && has1) g_key[r1] = 0ull;

    const float4 z = make_float4(0.f, 0.f, 0.f, 0.f);
    size_t ob0 = (size_t)r0 * 64;
    size_t ob1 = (size_t)r1 * 64;

    float4 a0 = z, a1 = z, b0 = z, b1 = z;
    if (key0 != 0ull) {
        size_t ib = (size_t)(~(unsigned int)(key0 & 0xFFFFFFFFull)) * 64;
        a0 = __ldg(&msg[ib + lane]);
        a1 = __ldg(&msg[ib + lane + 32]);
    }
    if (has1 && key1 != 0ull) {
        size_t ib = (size_t)(~(unsigned int)(key1 & 0xFFFFFFFFull)) * 64;
        b0 = __ldg(&msg[ib + lane]);
        b1 = __ldg(&msg[ib + lane + 32]);
    }
    stcs_f4(&out[ob0 + lane],      a0);
    stcs_f4(&out[ob0 + lane + 32], a1);
    if (has1) {
        stcs_f4(&out[ob1 + lane],      b0);
        stcs_f4(&out[ob1 + lane + 32], b1);
    }
}

// --- generic fallback (unexpected D): init + argmax + gather ----------------
__global__ void la_init_kernel(int N) {
    int i = blockIdx.x * blockDim.x + threadIdx.x;
    if (i < N) g_key[i] = 0ull;
}

__global__ void la_gather_generic_kernel(const float4* __restrict__ msg,
                                         float4* __restrict__ out,
                                         int N, int D4) {
    long long e = (long long)blockIdx.x * blockDim.x + threadIdx.x;
    long long total = (long long)N * D4;
    if (e >= total) return;
    int row  = (int)(e / D4);
    int lane = (int)(e % D4);
    unsigned long long key = g_key[row];
    float4 v = make_float4(0.f, 0.f, 0.f, 0.f);
    if (key != 0ull) {
        unsigned int win = ~(unsigned int)(key & 0xFFFFFFFFull);
        v = __ldg(&msg[(size_t)win * D4 + lane]);
    }
    out[(size_t)row * D4 + lane] = v;
}

extern "C" void kernel_launch(void* const* d_in, const int* in_sizes, int n_in,
                              void* d_out, int out_size) {
    // metadata order: msg [M*D f32], index [M i32], t [M f32], (dim_size)
    const float* msg   = (const float*)d_in[0];
    const int*   index = (const int*)d_in[1];
    const float* t     = (const float*)d_in[2];
    float*       out   = (float*)d_out;

    int M = in_sizes[1];              // 262144
    int D = in_sizes[0] / M;          // 256
    int N = out_size / D;             // 65536
    if (N > MAX_SEGMENTS) N = MAX_SEGMENTS;

    if (D == 256) {
        {   // argmax: 8 events/thread
            int threads = 256;
            int per_blk = threads * 8;
            int blocks  = (M + per_blk - 1) / per_blk;
            la_argmax_kernel<<<blocks, threads>>>(index, t, M, N);
        }
        {   // gather: 2 rows per warp, self-cleaning
            int threads = 256;                       // 8 warps = 16 rows/block
            int rows_per_blk = (threads / 32) * 2;
            int blocks = (N + rows_per_blk - 1) / rows_per_blk;
            la_gather_d256_kernel<<<blocks, threads>>>((const float4*)msg,
                                                       (float4*)out, N);
        }
    } else {
        // generic safe path
        {
            int threads = 256;
            int blocks  = (N + threads - 1) / threads;
            la_init_kernel<<<blocks, threads>>>(N);
        }
        {
            int threads = 256;
            int per_blk = threads * 8;
            int blocks  = (M + per_blk - 1) / per_blk;
            la_argmax_kernel<<<blocks, threads>>>(index, t, M, N);
        }
        {
            int D4 = D / 4;
            long long total = (long long)N * D4;
            int threads = 256;
            int blocks  = (int)((total + threads - 1) / threads);
            la_gather_generic_kernel<<<blocks, threads>>>((const float4*)msg,
                                                          (float4*)out, N, D4);
        }
    }
}